// round 8
// baseline (speedup 1.0000x reference)
#include <cuda_runtime.h>
#include <math.h>

#define BATCH 4096
#define NIN   512
#define NREP  512
#define NOUT  640
#define RW    512
#define RB    64
#define NNZ   16384

// Scratch (static device globals — allowed)
__device__ float g_t[RW];
__device__ float g_Wp[NOUT * NIN];
__device__ float g_bp[NOUT];
__device__ float g_lin[BATCH * NOUT];
__device__ float g_pre[NOUT * BATCH];     // preact, TRANSPOSED [ch][batch]
__device__ uint2 g_pair[NNZ];             // (src | col<<10, bits(param)), row-sorted
__device__ int   g_row_start[NOUT + 1];

// ---------------------------------------------------------------------------
// K0: zero g_t (also makes k3 the 4th launch -> gets ncu-profiled)
// ---------------------------------------------------------------------------
__global__ void kz(void) { g_t[threadIdx.x] = 0.0f; }

// ---------------------------------------------------------------------------
// K1: t = Qw^T @ wflat.  float4 loads: 512 thr = 4 row-groups x 128 col-thr.
// Each thread: 64 float4 LDGs (vs 256 scalar), 4 partial sums.
// ---------------------------------------------------------------------------
__global__ __launch_bounds__(512) void k1_qwt(const float* __restrict__ Qw,
                                              const float* __restrict__ w) {
    __shared__ float s_w[256];
    const int tid = threadIdx.x;
    const int rowBase = blockIdx.x * 256;
    if (tid < 256) s_w[tid] = w[rowBase + tid];
    __syncthreads();

    const int ct = tid & 127;          // column quad: cols 4*ct..+3
    const int rg = tid >> 7;           // row group 0..3 (64 rows each)
    const float4* p = reinterpret_cast<const float4*>(
        Qw + (size_t)(rowBase + rg * 64) * RW) + ct;
    const float* sw = s_w + rg * 64;

    float4 acc = make_float4(0.f, 0.f, 0.f, 0.f);
#pragma unroll 8
    for (int i = 0; i < 64; i++) {
        float4 q = p[i * 128];
        const float wv = sw[i];
        acc.x += q.x * wv; acc.y += q.y * wv;
        acc.z += q.z * wv; acc.w += q.w * wv;
    }
    atomicAdd(&g_t[ct * 4 + 0], acc.x);
    atomicAdd(&g_t[ct * 4 + 1], acc.y);
    atomicAdd(&g_t[ct * 4 + 2], acc.z);
    atomicAdd(&g_t[ct * 4 + 3], acc.w);
}

// ---------------------------------------------------------------------------
// K2: Wp[i] = dot(Qw[i,:], t)  (second Qw stream — at roofline)
// Blocks 0..2559: GEMV. Block 2560: CSR sort. Block 2561: bias.
// ---------------------------------------------------------------------------
__global__ __launch_bounds__(256) void k2_wp(
    const float* __restrict__ Qw,
    const int* __restrict__ bsrc, const int* __restrict__ brow,
    const int* __restrict__ bcol, const float* __restrict__ bp_params,
    const float* __restrict__ Qb, const float* __restrict__ b) {
    const int tid = threadIdx.x;

    if (blockIdx.x >= 2560) {
        if (blockIdx.x == 2560) {
            __shared__ int c[NOUT];
            __shared__ int scan[NOUT];
            __shared__ int off[NOUT];
            for (int i = tid; i < NOUT; i += 256) c[i] = 0;
            __syncthreads();
            for (int k = tid; k < NNZ; k += 256) atomicAdd(&c[brow[k]], 1);
            __syncthreads();
            if (tid < 32) {
                int base = 0;
#pragma unroll
                for (int ch = 0; ch < NOUT / 32; ch++) {
                    int v = c[ch * 32 + tid];
#pragma unroll
                    for (int d = 1; d < 32; d <<= 1) {
                        int n = __shfl_up_sync(0xffffffffu, v, d);
                        if (tid >= d) v += n;
                    }
                    scan[ch * 32 + tid] = v + base;
                    base += __shfl_sync(0xffffffffu, v, 31);
                }
            }
            __syncthreads();
            for (int i = tid; i < NOUT; i += 256) {
                const int s = scan[i] - c[i];
                g_row_start[i] = s;
                off[i] = s;
            }
            if (tid == 0) g_row_start[NOUT] = NNZ;
            __syncthreads();
            for (int k = tid; k < NNZ; k += 256) {
                const int r = brow[k];
                const int pos = atomicAdd(&off[r], 1);
                g_pair[pos] = make_uint2(
                    (unsigned)bsrc[k] | ((unsigned)bcol[k] << 10),
                    __float_as_uint(bp_params[k]));
            }
        } else {
            __shared__ float s_part[4][RB];
            __shared__ float s_s[RB];
            const int r = tid & 63;
            const int chunk = tid >> 6;
            float acc = 0.0f;
            for (int i = chunk * 160; i < chunk * 160 + 160; i++)
                acc += Qb[i * RB + r] * b[i];
            s_part[chunk][r] = acc;
            __syncthreads();
            if (tid < RB) {
                s_s[tid] = s_part[0][tid] + s_part[1][tid] +
                           s_part[2][tid] + s_part[3][tid];
            }
            __syncthreads();
            for (int j = tid; j < NOUT; j += 256) {
                const float4* q4 = reinterpret_cast<const float4*>(Qb + j * RB);
                const float4* s4 = reinterpret_cast<const float4*>(s_s);
                float a = 0.0f;
#pragma unroll
                for (int u = 0; u < 16; u++) {
                    float4 q = q4[u];
                    float4 s = s4[u];
                    a += q.x * s.x + q.y * s.y + q.z * s.z + q.w * s.w;
                }
                g_bp[j] = a;
            }
        }
        return;
    }

    __shared__ float s_t[RW];
    for (int i = tid; i < RW; i += 256) s_t[i] = g_t[i];
    __syncthreads();

    const int warp = tid >> 5;
    const int lane = tid & 31;
    const int row0 = (blockIdx.x * 8 + warp) * 16;
    const float4* t4 = reinterpret_cast<const float4*>(s_t);

    for (int rr = 0; rr < 16; rr++) {
        const int row = row0 + rr;
        const float4* p4 = reinterpret_cast<const float4*>(Qw + (size_t)row * RW);
        float acc = 0.0f;
#pragma unroll
        for (int u = 0; u < 4; u++) {
            float4 q = p4[lane + 32 * u];
            float4 tt = t4[lane + 32 * u];
            acc += q.x * tt.x + q.y * tt.y + q.z * tt.z + q.w * tt.w;
        }
#pragma unroll
        for (int off = 16; off > 0; off >>= 1)
            acc += __shfl_xor_sync(0xffffffffu, acc, off);
        if (lane == 0) g_Wp[row] = acc;
    }
}

// ---------------------------------------------------------------------------
// K3: lin = x @ Wp^T + bp   (4096x512 @ 512x640)  -- LAUNCH #4, profiled
// BM=64, BN=128, BK=16, 256 threads, grid (5,64)=320, 3 blocks/SM.
// ---------------------------------------------------------------------------
__global__ __launch_bounds__(256, 3) void k3_gemm(const float* __restrict__ x) {
    __shared__ float As2[16][128];   // row r duplicated at [2r],[2r+1]
    __shared__ float Bs[16][128];

    const int tid  = threadIdx.x;
    const int warp = tid >> 5;
    const int lane = tid & 31;
    const int bn0 = blockIdx.x * 128;
    const int bm0 = blockIdx.y * 64;

    const int am = tid & 63;
    const int ak = tid >> 6;
    const float* ap = x + (size_t)(bm0 + am) * NIN + ak * 4;
    const int bn_0 = tid & 127;
    const int bk_0 = tid >> 7;
    const float* bp0 = g_Wp + (size_t)(bn0 + bn_0) * NIN + bk_0 * 4;
    const float* bp1 = bp0 + 2 * 4;

    unsigned long long acc[8][2];
#pragma unroll
    for (int i = 0; i < 8; i++) { acc[i][0] = 0ull; acc[i][1] = 0ull; }

    float4 a4 = *reinterpret_cast<const float4*>(ap);
    float4 b4a = *reinterpret_cast<const float4*>(bp0);
    float4 b4b = *reinterpret_cast<const float4*>(bp1);

    for (int kt = 0; kt < 32; kt++) {
        {
            float2* d0 = reinterpret_cast<float2*>(&As2[ak * 4 + 0][am * 2]);
            float2* d1 = reinterpret_cast<float2*>(&As2[ak * 4 + 1][am * 2]);
            float2* d2 = reinterpret_cast<float2*>(&As2[ak * 4 + 2][am * 2]);
            float2* d3 = reinterpret_cast<float2*>(&As2[ak * 4 + 3][am * 2]);
            *d0 = make_float2(a4.x, a4.x);
            *d1 = make_float2(a4.y, a4.y);
            *d2 = make_float2(a4.z, a4.z);
            *d3 = make_float2(a4.w, a4.w);
            Bs[bk_0 * 4 + 0][bn_0] = b4a.x;
            Bs[bk_0 * 4 + 1][bn_0] = b4a.y;
            Bs[bk_0 * 4 + 2][bn_0] = b4a.z;
            Bs[bk_0 * 4 + 3][bn_0] = b4a.w;
            Bs[bk_0 * 4 + 8][bn_0] = b4b.x;
            Bs[bk_0 * 4 + 9][bn_0] = b4b.y;
            Bs[bk_0 * 4 + 10][bn_0] = b4b.z;
            Bs[bk_0 * 4 + 11][bn_0] = b4b.w;
        }
        __syncthreads();
        if (kt < 31) {
            a4  = *reinterpret_cast<const float4*>(ap  + (kt + 1) * 16);
            b4a = *reinterpret_cast<const float4*>(bp0 + (kt + 1) * 16);
            b4b = *reinterpret_cast<const float4*>(bp1 + (kt + 1) * 16);
        }
#pragma unroll
        for (int kk = 0; kk < 16; kk++) {
            ulonglong2 bb =
                *reinterpret_cast<const ulonglong2*>(&Bs[kk][lane * 4]);
#pragma unroll
            for (int i = 0; i < 8; i++) {
                unsigned long long a2 = *reinterpret_cast<const unsigned long long*>(
                    &As2[kk][(warp * 8 + i) * 2]);
                asm("fma.rn.f32x2 %0, %1, %2, %0;"
                    : "+l"(acc[i][0]) : "l"(a2), "l"(bb.x));
                asm("fma.rn.f32x2 %0, %1, %2, %0;"
                    : "+l"(acc[i][1]) : "l"(a2), "l"(bb.y));
            }
        }
        __syncthreads();
    }

    const float4 bv = *reinterpret_cast<const float4*>(&g_bp[bn0 + lane * 4]);
#pragma unroll
    for (int i = 0; i < 8; i++) {
        const int row = bm0 + warp * 8 + i;
        float r0, r1, r2, r3;
        asm("mov.b64 {%0, %1}, %2;" : "=f"(r0), "=f"(r1) : "l"(acc[i][0]));
        asm("mov.b64 {%0, %1}, %2;" : "=f"(r2), "=f"(r3) : "l"(acc[i][1]));
        float4 v = make_float4(r0 + bv.x, r1 + bv.y, r2 + bv.z, r3 + bv.w);
        *reinterpret_cast<float4*>(g_lin + (size_t)row * NOUT + bn0 + lane * 4) = v;
    }
}

// ---------------------------------------------------------------------------
// K4a: bilinear CSR -> preact, f32x2 dual-batch lanes, row-split x2.
// 4 independent accumulator chains per row (break the 4-cyc FMA RAW chain).
// ---------------------------------------------------------------------------
#define K4_P 33
extern __shared__ float2 k4_s2[];   // [640][33]

__global__ __launch_bounds__(512) void k4a_bilinear(void) {
    const int tid  = threadIdx.x;
    const int warp = tid >> 5;
    const int lane = tid & 31;
    const int grp  = blockIdx.x >> 1;
    const int half = blockIdx.x & 1;
    const int b0   = grp * 64;

    // Load 64 batch rows of lin into f32x2-packed smem.
#pragma unroll
    for (int i = 0; i < 4; i++) {
        const int bb = warp + 16 * i;
        const float* src = g_lin + (size_t)(b0 + bb) * NOUT;
        float* base = reinterpret_cast<float*>(k4_s2) + (bb & 1);
        const int pr = bb >> 1;
        for (int ch = lane; ch < NOUT; ch += 32)
            base[(ch * K4_P + pr) * 2] = src[ch];
    }
    __syncthreads();

    const unsigned long long* s_u64 =
        reinterpret_cast<const unsigned long long*>(k4_s2) + lane;
    unsigned long long c01;
    asm("mov.b64 %0, {%1, %1};" : "=l"(c01) : "f"(0.1f));

#pragma unroll 2
    for (int i = 0; i < 20; i++) {
        const int row = half * 320 + warp + 16 * i;
        const int ks = g_row_start[row];
        const int ke = g_row_start[row + 1];
        unsigned long long a0 = 0ull, a1 = 0ull, a2c = 0ull, a3 = 0ull;
        int k = ks;
        for (; k + 3 < ke; k += 4) {
            const uint2 p0 = g_pair[k + 0];
            const uint2 p1 = g_pair[k + 1];
            const uint2 p2 = g_pair[k + 2];
            const uint2 p3 = g_pair[k + 3];
#define K4_STEP(ACC, PR)                                                      \
            {                                                                 \
                unsigned long long av = s_u64[((PR).x & 1023) * K4_P];        \
                unsigned long long bv = s_u64[(((PR).x >> 10) & 1023) * K4_P];\
                const float pf = __uint_as_float((PR).y);                     \
                unsigned long long pp, t;                                     \
                asm("mov.b64 %0, {%1, %1};" : "=l"(pp) : "f"(pf));            \
                asm("mul.rn.f32x2 %0, %1, %2;" : "=l"(t) : "l"(av), "l"(bv)); \
                asm("fma.rn.f32x2 %0, %1, %2, %0;" : "+l"(ACC) : "l"(t), "l"(pp)); \
            }
            K4_STEP(a0, p0)
            K4_STEP(a1, p1)
            K4_STEP(a2c, p2)
            K4_STEP(a3, p3)
        }
        for (; k < ke; k++) {
            const uint2 p0 = g_pair[k];
            K4_STEP(a0, p0)
        }
        unsigned long long acc;
        asm("add.rn.f32x2 %0, %1, %2;" : "=l"(acc) : "l"(a0), "l"(a1));
        asm("add.rn.f32x2 %0, %1, %2;" : "+l"(acc) : "l"(acc), "l"(a2c));
        asm("add.rn.f32x2 %0, %1, %2;" : "+l"(acc) : "l"(acc), "l"(a3));

        unsigned long long linv = s_u64[row * K4_P];
        unsigned long long pv;
        asm("mul.rn.f32x2 %0, %1, %2;" : "=l"(pv) : "l"(acc), "l"(c01));
        asm("add.rn.f32x2 %0, %1, %2;" : "+l"(pv) : "l"(pv), "l"(linv));
        *reinterpret_cast<unsigned long long*>(
            g_pre + (size_t)row * BATCH + b0 + 2 * lane) = pv;
    }
}

// ---------------------------------------------------------------------------
// K4b: gated nonlinearity from transposed preact.
// ---------------------------------------------------------------------------
__global__ __launch_bounds__(256) void k4b_gate(
    const int* __restrict__ gate_idx, float* __restrict__ out) {
    __shared__ float s_t[32][257];
    const int tid = threadIdx.x;
    const int b0 = blockIdx.x * 256;
    const int j0 = blockIdx.y * 32;

#pragma unroll 4
    for (int jj = 0; jj < 32; jj++) {
        const int j = j0 + jj;
        const int gi = gate_idx[j];
        const float v = g_pre[(size_t)j * BATCH + b0 + tid];
        const float g = g_pre[(size_t)gi * BATCH + b0 + tid];
        s_t[jj][tid] = v / (1.0f + __expf(-g));
    }
    __syncthreads();

    float* dst = out + (size_t)(b0 + tid) * NREP + j0;
#pragma unroll
    for (int q = 0; q < 8; q++) {
        float4 v = make_float4(s_t[q * 4 + 0][tid], s_t[q * 4 + 1][tid],
                               s_t[q * 4 + 2][tid], s_t[q * 4 + 3][tid]);
        *reinterpret_cast<float4*>(dst + q * 4) = v;
    }
}

// ---------------------------------------------------------------------------
// Launch
// ---------------------------------------------------------------------------
extern "C" void kernel_launch(void* const* d_in, const int* in_sizes, int n_in,
                              void* d_out, int out_size) {
    const float* x        = (const float*)d_in[0];
    const float* W_weight = (const float*)d_in[1];
    const float* b        = (const float*)d_in[2];
    const float* Qw       = (const float*)d_in[3];
    const float* Qb       = (const float*)d_in[4];
    const float* bi_p     = (const float*)d_in[5];
    const int*   bi_src   = (const int*)d_in[6];
    const int*   bi_row   = (const int*)d_in[7];
    const int*   bi_col   = (const int*)d_in[8];
    const int*   gate_idx = (const int*)d_in[9];
    float* out = (float*)d_out;

    static int smem_set = 0;
    const int k4_smem_bytes = NOUT * K4_P * sizeof(float2);  // 168,960
    if (!smem_set) {
        cudaFuncSetAttribute(k4a_bilinear,
                             cudaFuncAttributeMaxDynamicSharedMemorySize,
                             k4_smem_bytes);
        smem_set = 1;
    }

    kz<<<1, 512>>>();
    k1_qwt<<<1280, 512>>>(Qw, W_weight);
    k2_wp<<<2562, 256>>>(Qw, bi_src, bi_row, bi_col, bi_p, Qb, b);
    k3_gemm<<<dim3(NOUT / 128, BATCH / 64), 256>>>(x);   // launch #4 -> profiled
    k4a_bilinear<<<128, 512, k4_smem_bytes>>>();
    k4b_gate<<<dim3(BATCH / 256, NREP / 32), 256>>>(gate_idx, out);
}

// round 9
// speedup vs baseline: 1.4603x; 1.4603x over previous
#include <cuda_runtime.h>
#include <math.h>

#define BATCH 4096
#define NIN   512
#define NREP  512
#define NOUT  640
#define RW    512
#define RB    64
#define NNZ   16384

// Scratch (static device globals — allowed)
__device__ float g_t[RW];
__device__ float g_Wp[NOUT * NIN];
__device__ float g_bp[NOUT];
__device__ float g_lin[BATCH * NOUT];
__device__ float g_pre[NOUT * BATCH];     // preact, TRANSPOSED [ch][batch]
__device__ uint2 g_pair[NNZ];             // (src | col<<10, bits(param)), row-sorted
__device__ int   g_row_start[NOUT + 1];

// ---------------------------------------------------------------------------
// K0: zero g_t (also keeps k3 at launch slot 4 -> ncu profiles it)
// ---------------------------------------------------------------------------
__global__ void kz(void) { g_t[threadIdx.x] = 0.0f; }

// ---------------------------------------------------------------------------
// K1: t = Qw^T @ wflat   (round-7 form, measured 107us at DRAM roofline)
// ---------------------------------------------------------------------------
__global__ __launch_bounds__(512) void k1_qwt(const float* __restrict__ Qw,
                                              const float* __restrict__ w) {
    __shared__ float s_w[256];
    const int tid = threadIdx.x;
    const int rowBase = blockIdx.x * 256;
    if (tid < 256) s_w[tid] = w[rowBase + tid];
    __syncthreads();

    float acc = 0.0f;
    const float* p = Qw + (size_t)rowBase * RW + tid;
#pragma unroll 8
    for (int i = 0; i < 256; i++) {
        acc += p[(size_t)i * RW] * s_w[i];
    }
    atomicAdd(&g_t[tid], acc);
}

// ---------------------------------------------------------------------------
// K2: Wp[i] = dot(Qw[i,:], t)  (second Qw stream — at roofline)
// Blocks 0..2559: GEMV. Block 2560: CSR sort. Block 2561: bias.
// ---------------------------------------------------------------------------
__global__ __launch_bounds__(256) void k2_wp(
    const float* __restrict__ Qw,
    const int* __restrict__ bsrc, const int* __restrict__ brow,
    const int* __restrict__ bcol, const float* __restrict__ bp_params,
    const float* __restrict__ Qb, const float* __restrict__ b) {
    const int tid = threadIdx.x;

    if (blockIdx.x >= 2560) {
        if (blockIdx.x == 2560) {
            __shared__ int c[NOUT];
            __shared__ int scan[NOUT];
            __shared__ int off[NOUT];
            for (int i = tid; i < NOUT; i += 256) c[i] = 0;
            __syncthreads();
            for (int k = tid; k < NNZ; k += 256) atomicAdd(&c[brow[k]], 1);
            __syncthreads();
            if (tid < 32) {
                int base = 0;
#pragma unroll
                for (int ch = 0; ch < NOUT / 32; ch++) {
                    int v = c[ch * 32 + tid];
#pragma unroll
                    for (int d = 1; d < 32; d <<= 1) {
                        int n = __shfl_up_sync(0xffffffffu, v, d);
                        if (tid >= d) v += n;
                    }
                    scan[ch * 32 + tid] = v + base;
                    base += __shfl_sync(0xffffffffu, v, 31);
                }
            }
            __syncthreads();
            for (int i = tid; i < NOUT; i += 256) {
                const int s = scan[i] - c[i];
                g_row_start[i] = s;
                off[i] = s;
            }
            if (tid == 0) g_row_start[NOUT] = NNZ;
            __syncthreads();
            for (int k = tid; k < NNZ; k += 256) {
                const int r = brow[k];
                const int pos = atomicAdd(&off[r], 1);
                g_pair[pos] = make_uint2(
                    (unsigned)bsrc[k] | ((unsigned)bcol[k] << 10),
                    __float_as_uint(bp_params[k]));
            }
        } else {
            __shared__ float s_part[4][RB];
            __shared__ float s_s[RB];
            const int r = tid & 63;
            const int chunk = tid >> 6;
            float acc = 0.0f;
            for (int i = chunk * 160; i < chunk * 160 + 160; i++)
                acc += Qb[i * RB + r] * b[i];
            s_part[chunk][r] = acc;
            __syncthreads();
            if (tid < RB) {
                s_s[tid] = s_part[0][tid] + s_part[1][tid] +
                           s_part[2][tid] + s_part[3][tid];
            }
            __syncthreads();
            for (int j = tid; j < NOUT; j += 256) {
                const float4* q4 = reinterpret_cast<const float4*>(Qb + j * RB);
                const float4* s4 = reinterpret_cast<const float4*>(s_s);
                float a = 0.0f;
#pragma unroll
                for (int u = 0; u < 16; u++) {
                    float4 q = q4[u];
                    float4 s = s4[u];
                    a += q.x * s.x + q.y * s.y + q.z * s.z + q.w * s.w;
                }
                g_bp[j] = a;
            }
        }
        return;
    }

    __shared__ float s_t[RW];
    for (int i = tid; i < RW; i += 256) s_t[i] = g_t[i];
    __syncthreads();

    const int warp = tid >> 5;
    const int lane = tid & 31;
    const int row0 = (blockIdx.x * 8 + warp) * 16;
    const float4* t4 = reinterpret_cast<const float4*>(s_t);

    for (int rr = 0; rr < 16; rr++) {
        const int row = row0 + rr;
        const float4* p4 = reinterpret_cast<const float4*>(Qw + (size_t)row * RW);
        float acc = 0.0f;
#pragma unroll
        for (int u = 0; u < 4; u++) {
            float4 q = p4[lane + 32 * u];
            float4 tt = t4[lane + 32 * u];
            acc += q.x * tt.x + q.y * tt.y + q.z * tt.z + q.w * tt.w;
        }
#pragma unroll
        for (int off = 16; off > 0; off >>= 1)
            acc += __shfl_xor_sync(0xffffffffu, acc, off);
        if (lane == 0) g_Wp[row] = acc;
    }
}

// ---------------------------------------------------------------------------
// K3: lin = x @ Wp^T + bp   (4096x512 @ 512x640)  -- LAUNCH #4, profiled
// BM=64, BN=128, BK=16, 128 threads, 8x8 per-thread f32x2 tile.
// LDS traffic: 64B per 64 FMA per thread (1 B/FMA) — was 2.5 B/FMA.
// Padded tiles: conflict-free compute reads, <=2-way store conflicts.
// grid (5, 64) = 320 blocks, ~4 blocks/SM co-resident.
// ---------------------------------------------------------------------------
__global__ __launch_bounds__(128) void k3_gemm(const float* __restrict__ x) {
    __shared__ float As[16][68];    // 68*4=272B rows (16B-aligned)
    __shared__ float Bs[16][132];   // 132*4=528B rows (16B-aligned)

    const int tid = threadIdx.x;
    const int tx = tid & 15;        // cols {tx*4..+3} and {64+tx*4..+3}
    const int ty = tid >> 4;        // rows ty*8 .. ty*8+7
    const int bn0 = blockIdx.x * 128;
    const int bm0 = blockIdx.y * 64;

    // A loader: 64 rows x 16 k = 256 float4, 2/thread
    const int am0 = (2 * tid + 0) >> 2, af0 = (2 * tid + 0) & 3;
    const int am1 = (2 * tid + 1) >> 2, af1 = (2 * tid + 1) & 3;
    const float* apg0 = x + (size_t)(bm0 + am0) * NIN + af0 * 4;
    const float* apg1 = x + (size_t)(bm0 + am1) * NIN + af1 * 4;
    // B loader: 128 rows x 16 k = 512 float4, 4/thread (idx = tid + 128*i)
    int bn_[4], bf_[4];
    const float* bpg[4];
#pragma unroll
    for (int i = 0; i < 4; i++) {
        const int idx = tid + 128 * i;
        bn_[i] = idx >> 2;
        bf_[i] = idx & 3;
        bpg[i] = g_Wp + (size_t)(bn0 + bn_[i]) * NIN + bf_[i] * 4;
    }

    unsigned long long acc[8][4];
#pragma unroll
    for (int i = 0; i < 8; i++)
#pragma unroll
        for (int j = 0; j < 4; j++) acc[i][j] = 0ull;

    float4 ar0 = *reinterpret_cast<const float4*>(apg0);
    float4 ar1 = *reinterpret_cast<const float4*>(apg1);
    float4 br[4];
#pragma unroll
    for (int i = 0; i < 4; i++) br[i] = *reinterpret_cast<const float4*>(bpg[i]);

    for (int kt = 0; kt < 32; kt++) {
        // store current tile
        As[af0 * 4 + 0][am0] = ar0.x; As[af0 * 4 + 1][am0] = ar0.y;
        As[af0 * 4 + 2][am0] = ar0.z; As[af0 * 4 + 3][am0] = ar0.w;
        As[af1 * 4 + 0][am1] = ar1.x; As[af1 * 4 + 1][am1] = ar1.y;
        As[af1 * 4 + 2][am1] = ar1.z; As[af1 * 4 + 3][am1] = ar1.w;
#pragma unroll
        for (int i = 0; i < 4; i++) {
            Bs[bf_[i] * 4 + 0][bn_[i]] = br[i].x;
            Bs[bf_[i] * 4 + 1][bn_[i]] = br[i].y;
            Bs[bf_[i] * 4 + 2][bn_[i]] = br[i].z;
            Bs[bf_[i] * 4 + 3][bn_[i]] = br[i].w;
        }
        __syncthreads();
        // prefetch next tile
        if (kt < 31) {
            ar0 = *reinterpret_cast<const float4*>(apg0 + (kt + 1) * 16);
            ar1 = *reinterpret_cast<const float4*>(apg1 + (kt + 1) * 16);
#pragma unroll
            for (int i = 0; i < 4; i++)
                br[i] = *reinterpret_cast<const float4*>(bpg[i] + (kt + 1) * 16);
        }
#pragma unroll
        for (int kk = 0; kk < 16; kk++) {
            const float4 a0 = *reinterpret_cast<const float4*>(&As[kk][ty * 8]);
            const float4 a1 = *reinterpret_cast<const float4*>(&As[kk][ty * 8 + 4]);
            const ulonglong2 bL =
                *reinterpret_cast<const ulonglong2*>(&Bs[kk][tx * 4]);
            const ulonglong2 bH =
                *reinterpret_cast<const ulonglong2*>(&Bs[kk][64 + tx * 4]);
            unsigned long long a2[8];
            asm("mov.b64 %0, {%1, %1};" : "=l"(a2[0]) : "f"(a0.x));
            asm("mov.b64 %0, {%1, %1};" : "=l"(a2[1]) : "f"(a0.y));
            asm("mov.b64 %0, {%1, %1};" : "=l"(a2[2]) : "f"(a0.z));
            asm("mov.b64 %0, {%1, %1};" : "=l"(a2[3]) : "f"(a0.w));
            asm("mov.b64 %0, {%1, %1};" : "=l"(a2[4]) : "f"(a1.x));
            asm("mov.b64 %0, {%1, %1};" : "=l"(a2[5]) : "f"(a1.y));
            asm("mov.b64 %0, {%1, %1};" : "=l"(a2[6]) : "f"(a1.z));
            asm("mov.b64 %0, {%1, %1};" : "=l"(a2[7]) : "f"(a1.w));
#pragma unroll
            for (int i = 0; i < 8; i++) {
                asm("fma.rn.f32x2 %0, %1, %2, %0;" : "+l"(acc[i][0]) : "l"(a2[i]), "l"(bL.x));
                asm("fma.rn.f32x2 %0, %1, %2, %0;" : "+l"(acc[i][1]) : "l"(a2[i]), "l"(bL.y));
                asm("fma.rn.f32x2 %0, %1, %2, %0;" : "+l"(acc[i][2]) : "l"(a2[i]), "l"(bH.x));
                asm("fma.rn.f32x2 %0, %1, %2, %0;" : "+l"(acc[i][3]) : "l"(a2[i]), "l"(bH.y));
            }
        }
        __syncthreads();
    }

    // epilogue: unpack, add bias, store 2x float4 per row
    const float4 bv0 = *reinterpret_cast<const float4*>(&g_bp[bn0 + tx * 4]);
    const float4 bv1 = *reinterpret_cast<const float4*>(&g_bp[bn0 + 64 + tx * 4]);
#pragma unroll
    for (int i = 0; i < 8; i++) {
        const int row = bm0 + ty * 8 + i;
        float r0, r1, r2, r3, r4, r5, r6, r7;
        asm("mov.b64 {%0, %1}, %2;" : "=f"(r0), "=f"(r1) : "l"(acc[i][0]));
        asm("mov.b64 {%0, %1}, %2;" : "=f"(r2), "=f"(r3) : "l"(acc[i][1]));
        asm("mov.b64 {%0, %1}, %2;" : "=f"(r4), "=f"(r5) : "l"(acc[i][2]));
        asm("mov.b64 {%0, %1}, %2;" : "=f"(r6), "=f"(r7) : "l"(acc[i][3]));
        float* dst = g_lin + (size_t)row * NOUT + bn0;
        *reinterpret_cast<float4*>(dst + tx * 4) =
            make_float4(r0 + bv0.x, r1 + bv0.y, r2 + bv0.z, r3 + bv0.w);
        *reinterpret_cast<float4*>(dst + 64 + tx * 4) =
            make_float4(r4 + bv1.x, r5 + bv1.y, r6 + bv1.z, r7 + bv1.w);
    }
}

// ---------------------------------------------------------------------------
// K4a: bilinear CSR -> preact (round-7 form, measured 54.5us)
// ---------------------------------------------------------------------------
#define K4_P 33
extern __shared__ float2 k4_s2[];   // [640][33]

__global__ __launch_bounds__(512) void k4a_bilinear(void) {
    const int tid  = threadIdx.x;
    const int warp = tid >> 5;
    const int lane = tid & 31;
    const int grp  = blockIdx.x >> 1;
    const int half = blockIdx.x & 1;
    const int b0   = grp * 64;

#pragma unroll
    for (int i = 0; i < 4; i++) {
        const int bb = warp + 16 * i;
        const float* src = g_lin + (size_t)(b0 + bb) * NOUT;
        float* base = reinterpret_cast<float*>(k4_s2) + (bb & 1);
        const int pr = bb >> 1;
        for (int ch = lane; ch < NOUT; ch += 32)
            base[(ch * K4_P + pr) * 2] = src[ch];
    }
    __syncthreads();

    const unsigned long long* s_u64 =
        reinterpret_cast<const unsigned long long*>(k4_s2) + lane;
    unsigned long long c01;
    asm("mov.b64 %0, {%1, %1};" : "=l"(c01) : "f"(0.1f));

#pragma unroll 2
    for (int i = 0; i < 20; i++) {
        const int row = half * 320 + warp + 16 * i;
        const int ks = g_row_start[row];
        const int ke = g_row_start[row + 1];
        unsigned long long acc = 0ull;
        int k = ks;
        for (; k + 3 < ke; k += 4) {
#pragma unroll
            for (int u = 0; u < 4; u++) {
                const uint2 pr = g_pair[k + u];
                unsigned long long av = s_u64[(pr.x & 1023) * K4_P];
                unsigned long long bv = s_u64[((pr.x >> 10) & 1023) * K4_P];
                const float pf = __uint_as_float(pr.y);
                unsigned long long p2, t;
                asm("mov.b64 %0, {%1, %1};" : "=l"(p2) : "f"(pf));
                asm("mul.rn.f32x2 %0, %1, %2;" : "=l"(t) : "l"(av), "l"(bv));
                asm("fma.rn.f32x2 %0, %1, %2, %0;" : "+l"(acc) : "l"(t), "l"(p2));
            }
        }
        for (; k < ke; k++) {
            const uint2 pr = g_pair[k];
            unsigned long long av = s_u64[(pr.x & 1023) * K4_P];
            unsigned long long bv = s_u64[((pr.x >> 10) & 1023) * K4_P];
            const float pf = __uint_as_float(pr.y);
            unsigned long long p2, t;
            asm("mov.b64 %0, {%1, %1};" : "=l"(p2) : "f"(pf));
            asm("mul.rn.f32x2 %0, %1, %2;" : "=l"(t) : "l"(av), "l"(bv));
            asm("fma.rn.f32x2 %0, %1, %2, %0;" : "+l"(acc) : "l"(t), "l"(p2));
        }
        unsigned long long linv = s_u64[row * K4_P];
        unsigned long long pv;
        asm("mul.rn.f32x2 %0, %1, %2;" : "=l"(pv) : "l"(acc), "l"(c01));
        asm("add.rn.f32x2 %0, %1, %2;" : "+l"(pv) : "l"(pv), "l"(linv));
        *reinterpret_cast<unsigned long long*>(
            g_pre + (size_t)row * BATCH + b0 + 2 * lane) = pv;
    }
}

// ---------------------------------------------------------------------------
// K4b: gated nonlinearity from transposed preact (round-7 form, ~6us)
// ---------------------------------------------------------------------------
__global__ __launch_bounds__(256) void k4b_gate(
    const int* __restrict__ gate_idx, float* __restrict__ out) {
    __shared__ float s_t[32][257];
    const int tid = threadIdx.x;
    const int b0 = blockIdx.x * 256;
    const int j0 = blockIdx.y * 32;

#pragma unroll 4
    for (int jj = 0; jj < 32; jj++) {
        const int j = j0 + jj;
        const int gi = gate_idx[j];
        const float v = g_pre[(size_t)j * BATCH + b0 + tid];
        const float g = g_pre[(size_t)gi * BATCH + b0 + tid];
        s_t[jj][tid] = v / (1.0f + __expf(-g));
    }
    __syncthreads();

    float* dst = out + (size_t)(b0 + tid) * NREP + j0;
#pragma unroll
    for (int q = 0; q < 8; q++) {
        float4 v = make_float4(s_t[q * 4 + 0][tid], s_t[q * 4 + 1][tid],
                               s_t[q * 4 + 2][tid], s_t[q * 4 + 3][tid]);
        *reinterpret_cast<float4*>(dst + q * 4) = v;
    }
}

// ---------------------------------------------------------------------------
// Launch
// ---------------------------------------------------------------------------
extern "C" void kernel_launch(void* const* d_in, const int* in_sizes, int n_in,
                              void* d_out, int out_size) {
    const float* x        = (const float*)d_in[0];
    const float* W_weight = (const float*)d_in[1];
    const float* b        = (const float*)d_in[2];
    const float* Qw       = (const float*)d_in[3];
    const float* Qb       = (const float*)d_in[4];
    const float* bi_p     = (const float*)d_in[5];
    const int*   bi_src   = (const int*)d_in[6];
    const int*   bi_row   = (const int*)d_in[7];
    const int*   bi_col   = (const int*)d_in[8];
    const int*   gate_idx = (const int*)d_in[9];
    float* out = (float*)d_out;

    static int smem_set = 0;
    const int k4_smem_bytes = NOUT * K4_P * sizeof(float2);  // 168,960
    if (!smem_set) {
        cudaFuncSetAttribute(k4a_bilinear,
                             cudaFuncAttributeMaxDynamicSharedMemorySize,
                             k4_smem_bytes);
        smem_set = 1;
    }

    kz<<<1, 512>>>();
    k1_qwt<<<1280, 512>>>(Qw, W_weight);
    k2_wp<<<2562, 256>>>(Qw, bi_src, bi_row, bi_col, bi_p, Qb, b);
    k3_gemm<<<dim3(NOUT / 128, BATCH / 64), 128>>>(x);   // launch #4 -> profiled
    k4a_bilinear<<<128, 512, k4_smem_bytes>>>();
    k4b_gate<<<dim3(BATCH / 256, NREP / 32), 256>>>(gate_idx, out);
}

// round 10
// speedup vs baseline: 1.5170x; 1.0389x over previous
#include <cuda_runtime.h>
#include <math.h>

#define BATCH 4096
#define NIN   512
#define NREP  512
#define NOUT  640
#define RW    512
#define RB    64
#define NNZ   16384

// Scratch (static device globals — allowed)
__device__ float g_t[RW];
__device__ float g_Wp[NOUT * NIN];
__device__ float g_bp[NOUT];
__device__ float g_lin[BATCH * NOUT];     // K-half 0 partial (+bias)
__device__ float g_lin2[BATCH * NOUT];    // K-half 1 partial
__device__ float g_pre[NOUT * BATCH];     // preact, TRANSPOSED [ch][batch]
__device__ uint2 g_pair[NNZ];             // (src | col<<10, bits(param)), row-sorted
__device__ int   g_row_start[NOUT + 1];

// ---------------------------------------------------------------------------
// K0: zero g_t (also keeps k3 at launch slot 4 -> ncu profiles it)
// ---------------------------------------------------------------------------
__global__ void kz(void) { g_t[threadIdx.x] = 0.0f; }

// ---------------------------------------------------------------------------
// K1: t = Qw^T @ wflat   (measured at DRAM roofline — FROZEN)
// ---------------------------------------------------------------------------
__global__ __launch_bounds__(512) void k1_qwt(const float* __restrict__ Qw,
                                              const float* __restrict__ w) {
    __shared__ float s_w[256];
    const int tid = threadIdx.x;
    const int rowBase = blockIdx.x * 256;
    if (tid < 256) s_w[tid] = w[rowBase + tid];
    __syncthreads();

    float acc = 0.0f;
    const float* p = Qw + (size_t)rowBase * RW + tid;
#pragma unroll 8
    for (int i = 0; i < 256; i++) {
        acc += p[(size_t)i * RW] * s_w[i];
    }
    atomicAdd(&g_t[tid], acc);
}

// ---------------------------------------------------------------------------
// K2: Wp[i] = dot(Qw[i,:], t)  (second Qw stream — at roofline, FROZEN)
// Blocks 0..2559: GEMV. Block 2560: CSR sort. Block 2561: bias.
// ---------------------------------------------------------------------------
__global__ __launch_bounds__(256) void k2_wp(
    const float* __restrict__ Qw,
    const int* __restrict__ bsrc, const int* __restrict__ brow,
    const int* __restrict__ bcol, const float* __restrict__ bp_params,
    const float* __restrict__ Qb, const float* __restrict__ b) {
    const int tid = threadIdx.x;

    if (blockIdx.x >= 2560) {
        if (blockIdx.x == 2560) {
            __shared__ int c[NOUT];
            __shared__ int scan[NOUT];
            __shared__ int off[NOUT];
            for (int i = tid; i < NOUT; i += 256) c[i] = 0;
            __syncthreads();
            for (int k = tid; k < NNZ; k += 256) atomicAdd(&c[brow[k]], 1);
            __syncthreads();
            if (tid < 32) {
                int base = 0;
#pragma unroll
                for (int ch = 0; ch < NOUT / 32; ch++) {
                    int v = c[ch * 32 + tid];
#pragma unroll
                    for (int d = 1; d < 32; d <<= 1) {
                        int n = __shfl_up_sync(0xffffffffu, v, d);
                        if (tid >= d) v += n;
                    }
                    scan[ch * 32 + tid] = v + base;
                    base += __shfl_sync(0xffffffffu, v, 31);
                }
            }
            __syncthreads();
            for (int i = tid; i < NOUT; i += 256) {
                const int s = scan[i] - c[i];
                g_row_start[i] = s;
                off[i] = s;
            }
            if (tid == 0) g_row_start[NOUT] = NNZ;
            __syncthreads();
            for (int k = tid; k < NNZ; k += 256) {
                const int r = brow[k];
                const int pos = atomicAdd(&off[r], 1);
                g_pair[pos] = make_uint2(
                    (unsigned)bsrc[k] | ((unsigned)bcol[k] << 10),
                    __float_as_uint(bp_params[k]));
            }
        } else {
            __shared__ float s_part[4][RB];
            __shared__ float s_s[RB];
            const int r = tid & 63;
            const int chunk = tid >> 6;
            float acc = 0.0f;
            for (int i = chunk * 160; i < chunk * 160 + 160; i++)
                acc += Qb[i * RB + r] * b[i];
            s_part[chunk][r] = acc;
            __syncthreads();
            if (tid < RB) {
                s_s[tid] = s_part[0][tid] + s_part[1][tid] +
                           s_part[2][tid] + s_part[3][tid];
            }
            __syncthreads();
            for (int j = tid; j < NOUT; j += 256) {
                const float4* q4 = reinterpret_cast<const float4*>(Qb + j * RB);
                const float4* s4 = reinterpret_cast<const float4*>(s_s);
                float a = 0.0f;
#pragma unroll
                for (int u = 0; u < 16; u++) {
                    float4 q = q4[u];
                    float4 s = s4[u];
                    a += q.x * s.x + q.y * s.y + q.z * s.z + q.w * s.w;
                }
                g_bp[j] = a;
            }
        }
        return;
    }

    __shared__ float s_t[RW];
    for (int i = tid; i < RW; i += 256) s_t[i] = g_t[i];
    __syncthreads();

    const int warp = tid >> 5;
    const int lane = tid & 31;
    const int row0 = (blockIdx.x * 8 + warp) * 16;
    const float4* t4 = reinterpret_cast<const float4*>(s_t);

    for (int rr = 0; rr < 16; rr++) {
        const int row = row0 + rr;
        const float4* p4 = reinterpret_cast<const float4*>(Qw + (size_t)row * RW);
        float acc = 0.0f;
#pragma unroll
        for (int u = 0; u < 4; u++) {
            float4 q = p4[lane + 32 * u];
            float4 tt = t4[lane + 32 * u];
            acc += q.x * tt.x + q.y * tt.y + q.z * tt.z + q.w * tt.w;
        }
#pragma unroll
        for (int off = 16; off > 0; off >>= 1)
            acc += __shfl_xor_sync(0xffffffffu, acc, off);
        if (lane == 0) g_Wp[row] = acc;
    }
}

// ---------------------------------------------------------------------------
// K3: lin = x @ Wp^T + bp, SPLIT-K x2  (4096x512 @ 512x640)
// BM=64, BN=128, BK=16, 128 threads, 8x8 per-thread f32x2 tile (1 B/FMA).
// grid (5, 64, 2) = 640 blocks -> 3 resident/SM (was grid-limited at 2.16).
// z=0 -> g_lin (+bias), z=1 -> g_lin2; k4a sums the halves on load.
// ---------------------------------------------------------------------------
__global__ __launch_bounds__(128) void k3_gemm(const float* __restrict__ x) {
    __shared__ float As[16][68];
    __shared__ float Bs[16][132];

    const int tid = threadIdx.x;
    const int tx = tid & 15;
    const int ty = tid >> 4;
    const int bn0 = blockIdx.x * 128;
    const int bm0 = blockIdx.y * 64;
    const int kb  = blockIdx.z * 256;     // K half base

    const int am0 = (2 * tid + 0) >> 2, af0 = (2 * tid + 0) & 3;
    const int am1 = (2 * tid + 1) >> 2, af1 = (2 * tid + 1) & 3;
    const float* apg0 = x + (size_t)(bm0 + am0) * NIN + kb + af0 * 4;
    const float* apg1 = x + (size_t)(bm0 + am1) * NIN + kb + af1 * 4;
    int bn_[4], bf_[4];
    const float* bpg[4];
#pragma unroll
    for (int i = 0; i < 4; i++) {
        const int idx = tid + 128 * i;
        bn_[i] = idx >> 2;
        bf_[i] = idx & 3;
        bpg[i] = g_Wp + (size_t)(bn0 + bn_[i]) * NIN + kb + bf_[i] * 4;
    }

    unsigned long long acc[8][4];
#pragma unroll
    for (int i = 0; i < 8; i++)
#pragma unroll
        for (int j = 0; j < 4; j++) acc[i][j] = 0ull;

    float4 ar0 = *reinterpret_cast<const float4*>(apg0);
    float4 ar1 = *reinterpret_cast<const float4*>(apg1);
    float4 br[4];
#pragma unroll
    for (int i = 0; i < 4; i++) br[i] = *reinterpret_cast<const float4*>(bpg[i]);

    for (int kt = 0; kt < 16; kt++) {
        As[af0 * 4 + 0][am0] = ar0.x; As[af0 * 4 + 1][am0] = ar0.y;
        As[af0 * 4 + 2][am0] = ar0.z; As[af0 * 4 + 3][am0] = ar0.w;
        As[af1 * 4 + 0][am1] = ar1.x; As[af1 * 4 + 1][am1] = ar1.y;
        As[af1 * 4 + 2][am1] = ar1.z; As[af1 * 4 + 3][am1] = ar1.w;
#pragma unroll
        for (int i = 0; i < 4; i++) {
            Bs[bf_[i] * 4 + 0][bn_[i]] = br[i].x;
            Bs[bf_[i] * 4 + 1][bn_[i]] = br[i].y;
            Bs[bf_[i] * 4 + 2][bn_[i]] = br[i].z;
            Bs[bf_[i] * 4 + 3][bn_[i]] = br[i].w;
        }
        __syncthreads();
        if (kt < 15) {
            ar0 = *reinterpret_cast<const float4*>(apg0 + (kt + 1) * 16);
            ar1 = *reinterpret_cast<const float4*>(apg1 + (kt + 1) * 16);
#pragma unroll
            for (int i = 0; i < 4; i++)
                br[i] = *reinterpret_cast<const float4*>(bpg[i] + (kt + 1) * 16);
        }
#pragma unroll
        for (int kk = 0; kk < 16; kk++) {
            const float4 a0 = *reinterpret_cast<const float4*>(&As[kk][ty * 8]);
            const float4 a1 = *reinterpret_cast<const float4*>(&As[kk][ty * 8 + 4]);
            const ulonglong2 bL =
                *reinterpret_cast<const ulonglong2*>(&Bs[kk][tx * 4]);
            const ulonglong2 bH =
                *reinterpret_cast<const ulonglong2*>(&Bs[kk][64 + tx * 4]);
            unsigned long long a2[8];
            asm("mov.b64 %0, {%1, %1};" : "=l"(a2[0]) : "f"(a0.x));
            asm("mov.b64 %0, {%1, %1};" : "=l"(a2[1]) : "f"(a0.y));
            asm("mov.b64 %0, {%1, %1};" : "=l"(a2[2]) : "f"(a0.z));
            asm("mov.b64 %0, {%1, %1};" : "=l"(a2[3]) : "f"(a0.w));
            asm("mov.b64 %0, {%1, %1};" : "=l"(a2[4]) : "f"(a1.x));
            asm("mov.b64 %0, {%1, %1};" : "=l"(a2[5]) : "f"(a1.y));
            asm("mov.b64 %0, {%1, %1};" : "=l"(a2[6]) : "f"(a1.z));
            asm("mov.b64 %0, {%1, %1};" : "=l"(a2[7]) : "f"(a1.w));
#pragma unroll
            for (int i = 0; i < 8; i++) {
                asm("fma.rn.f32x2 %0, %1, %2, %0;" : "+l"(acc[i][0]) : "l"(a2[i]), "l"(bL.x));
                asm("fma.rn.f32x2 %0, %1, %2, %0;" : "+l"(acc[i][1]) : "l"(a2[i]), "l"(bL.y));
                asm("fma.rn.f32x2 %0, %1, %2, %0;" : "+l"(acc[i][2]) : "l"(a2[i]), "l"(bH.x));
                asm("fma.rn.f32x2 %0, %1, %2, %0;" : "+l"(acc[i][3]) : "l"(a2[i]), "l"(bH.y));
            }
        }
        __syncthreads();
    }

    // epilogue: z=0 adds bias -> g_lin; z=1 raw partial -> g_lin2
    float* gout = (blockIdx.z == 0) ? g_lin : g_lin2;
    float4 bv0 = make_float4(0.f, 0.f, 0.f, 0.f);
    float4 bv1 = make_float4(0.f, 0.f, 0.f, 0.f);
    if (blockIdx.z == 0) {
        bv0 = *reinterpret_cast<const float4*>(&g_bp[bn0 + tx * 4]);
        bv1 = *reinterpret_cast<const float4*>(&g_bp[bn0 + 64 + tx * 4]);
    }
#pragma unroll
    for (int i = 0; i < 8; i++) {
        const int row = bm0 + ty * 8 + i;
        float r0, r1, r2, r3, r4, r5, r6, r7;
        asm("mov.b64 {%0, %1}, %2;" : "=f"(r0), "=f"(r1) : "l"(acc[i][0]));
        asm("mov.b64 {%0, %1}, %2;" : "=f"(r2), "=f"(r3) : "l"(acc[i][1]));
        asm("mov.b64 {%0, %1}, %2;" : "=f"(r4), "=f"(r5) : "l"(acc[i][2]));
        asm("mov.b64 {%0, %1}, %2;" : "=f"(r6), "=f"(r7) : "l"(acc[i][3]));
        float* dst = gout + (size_t)row * NOUT + bn0;
        *reinterpret_cast<float4*>(dst + tx * 4) =
            make_float4(r0 + bv0.x, r1 + bv0.y, r2 + bv0.z, r3 + bv0.w);
        *reinterpret_cast<float4*>(dst + 64 + tx * 4) =
            make_float4(r4 + bv1.x, r5 + bv1.y, r6 + bv1.z, r7 + bv1.w);
    }
}

// ---------------------------------------------------------------------------
// K4a: bilinear CSR -> preact; sums the two K-half partials on load.
// 4 independent accumulator chains (breaks 8-cyc mul->fma RAW chain).
// ---------------------------------------------------------------------------
#define K4_P 33
extern __shared__ float2 k4_s2[];   // [640][33]

__global__ __launch_bounds__(512) void k4a_bilinear(void) {
    const int tid  = threadIdx.x;
    const int warp = tid >> 5;
    const int lane = tid & 31;
    const int grp  = blockIdx.x >> 1;
    const int half = blockIdx.x & 1;
    const int b0   = grp * 64;

#pragma unroll
    for (int i = 0; i < 4; i++) {
        const int bb = warp + 16 * i;
        const float* src1 = g_lin  + (size_t)(b0 + bb) * NOUT;
        const float* src2 = g_lin2 + (size_t)(b0 + bb) * NOUT;
        float* base = reinterpret_cast<float*>(k4_s2) + (bb & 1);
        const int pr = bb >> 1;
        for (int ch = lane; ch < NOUT; ch += 32)
            base[(ch * K4_P + pr) * 2] = src1[ch] + src2[ch];
    }
    __syncthreads();

    const unsigned long long* s_u64 =
        reinterpret_cast<const unsigned long long*>(k4_s2) + lane;
    unsigned long long c01;
    asm("mov.b64 %0, {%1, %1};" : "=l"(c01) : "f"(0.1f));

#pragma unroll 2
    for (int i = 0; i < 20; i++) {
        const int row = half * 320 + warp + 16 * i;
        const int ks = g_row_start[row];
        const int ke = g_row_start[row + 1];
        unsigned long long a0 = 0ull, a1 = 0ull, a2c = 0ull, a3 = 0ull;
        int k = ks;
#define K4_STEP(ACC, PR)                                                      \
        {                                                                     \
            unsigned long long av = s_u64[((PR).x & 1023) * K4_P];            \
            unsigned long long bv = s_u64[(((PR).x >> 10) & 1023) * K4_P];    \
            const float pf = __uint_as_float((PR).y);                         \
            unsigned long long pp, t;                                         \
            asm("mov.b64 %0, {%1, %1};" : "=l"(pp) : "f"(pf));                \
            asm("mul.rn.f32x2 %0, %1, %2;" : "=l"(t) : "l"(av), "l"(bv));     \
            asm("fma.rn.f32x2 %0, %1, %2, %0;" : "+l"(ACC) : "l"(t), "l"(pp));\
        }
        for (; k + 3 < ke; k += 4) {
            const uint2 p0 = g_pair[k + 0];
            const uint2 p1 = g_pair[k + 1];
            const uint2 p2 = g_pair[k + 2];
            const uint2 p3 = g_pair[k + 3];
            K4_STEP(a0, p0)
            K4_STEP(a1, p1)
            K4_STEP(a2c, p2)
            K4_STEP(a3, p3)
        }
        for (; k < ke; k++) {
            const uint2 p0 = g_pair[k];
            K4_STEP(a0, p0)
        }
        unsigned long long acc;
        asm("add.rn.f32x2 %0, %1, %2;" : "=l"(acc) : "l"(a0), "l"(a1));
        asm("add.rn.f32x2 %0, %1, %2;" : "+l"(acc) : "l"(acc), "l"(a2c));
        asm("add.rn.f32x2 %0, %1, %2;" : "+l"(acc) : "l"(acc), "l"(a3));

        unsigned long long linv = s_u64[row * K4_P];
        unsigned long long pv;
        asm("mul.rn.f32x2 %0, %1, %2;" : "=l"(pv) : "l"(acc), "l"(c01));
        asm("add.rn.f32x2 %0, %1, %2;" : "+l"(pv) : "l"(pv), "l"(linv));
        *reinterpret_cast<unsigned long long*>(
            g_pre + (size_t)row * BATCH + b0 + 2 * lane) = pv;
    }
}

// ---------------------------------------------------------------------------
// K4b: gated nonlinearity from transposed preact (FROZEN, ~6us)
// ---------------------------------------------------------------------------
__global__ __launch_bounds__(256) void k4b_gate(
    const int* __restrict__ gate_idx, float* __restrict__ out) {
    __shared__ float s_t[32][257];
    const int tid = threadIdx.x;
    const int b0 = blockIdx.x * 256;
    const int j0 = blockIdx.y * 32;

#pragma unroll 4
    for (int jj = 0; jj < 32; jj++) {
        const int j = j0 + jj;
        const int gi = gate_idx[j];
        const float v = g_pre[(size_t)j * BATCH + b0 + tid];
        const float g = g_pre[(size_t)gi * BATCH + b0 + tid];
        s_t[jj][tid] = v / (1.0f + __expf(-g));
    }
    __syncthreads();

    float* dst = out + (size_t)(b0 + tid) * NREP + j0;
#pragma unroll
    for (int q = 0; q < 8; q++) {
        float4 v = make_float4(s_t[q * 4 + 0][tid], s_t[q * 4 + 1][tid],
                               s_t[q * 4 + 2][tid], s_t[q * 4 + 3][tid]);
        *reinterpret_cast<float4*>(dst + q * 4) = v;
    }
}

// ---------------------------------------------------------------------------
// Launch
// ---------------------------------------------------------------------------
extern "C" void kernel_launch(void* const* d_in, const int* in_sizes, int n_in,
                              void* d_out, int out_size) {
    const float* x        = (const float*)d_in[0];
    const float* W_weight = (const float*)d_in[1];
    const float* b        = (const float*)d_in[2];
    const float* Qw       = (const float*)d_in[3];
    const float* Qb       = (const float*)d_in[4];
    const float* bi_p     = (const float*)d_in[5];
    const int*   bi_src   = (const int*)d_in[6];
    const int*   bi_row   = (const int*)d_in[7];
    const int*   bi_col   = (const int*)d_in[8];
    const int*   gate_idx = (const int*)d_in[9];
    float* out = (float*)d_out;

    static int smem_set = 0;
    const int k4_smem_bytes = NOUT * K4_P * sizeof(float2);  // 168,960
    if (!smem_set) {
        cudaFuncSetAttribute(k4a_bilinear,
                             cudaFuncAttributeMaxDynamicSharedMemorySize,
                             k4_smem_bytes);
        smem_set = 1;
    }

    kz<<<1, 512>>>();
    k1_qwt<<<1280, 512>>>(Qw, W_weight);
    k2_wp<<<2562, 256>>>(Qw, bi_src, bi_row, bi_col, bi_p, Qb, b);
    k3_gemm<<<dim3(NOUT / 128, BATCH / 64, 2), 128>>>(x);  // launch #4 -> profiled
    k4a_bilinear<<<128, 512, k4_smem_bytes>>>();
    k4b_gate<<<dim3(BATCH / 256, NREP / 32), 256>>>(gate_idx, out);
}

// round 11
// speedup vs baseline: 1.5297x; 1.0084x over previous
#include <cuda_runtime.h>
#include <math.h>

#define BATCH 4096
#define NIN   512
#define NREP  512
#define NOUT  640
#define RW    512
#define RB    64
#define NNZ   16384

// Scratch (static device globals — allowed)
__device__ float g_t[RW];                 // zero at load; re-zeroed by k4a blk0
__device__ float g_Wp[NOUT * NIN];
__device__ float g_bp[NOUT];
__device__ float g_lin[BATCH * NOUT];     // K-half 0 partial (+bias)
__device__ float g_lin2[BATCH * NOUT];    // K-half 1 partial
__device__ float g_pre[NOUT * BATCH];     // preact, TRANSPOSED [ch][batch]
__device__ uint2 g_pair[NNZ];             // (src | col<<10, bits(param)), row-sorted
__device__ int   g_row_start[NOUT + 1];

// ---------------------------------------------------------------------------
// K1: t = Qw^T @ wflat   (measured at DRAM roofline — FROZEN)
// ---------------------------------------------------------------------------
__global__ __launch_bounds__(512) void k1_qwt(const float* __restrict__ Qw,
                                              const float* __restrict__ w) {
    __shared__ float s_w[256];
    const int tid = threadIdx.x;
    const int rowBase = blockIdx.x * 256;
    if (tid < 256) s_w[tid] = w[rowBase + tid];
    __syncthreads();

    float acc = 0.0f;
    const float* p = Qw + (size_t)rowBase * RW + tid;
#pragma unroll 8
    for (int i = 0; i < 256; i++) {
        acc += p[(size_t)i * RW] * s_w[i];
    }
    atomicAdd(&g_t[tid], acc);
}

// ---------------------------------------------------------------------------
// K2: Wp[i] = dot(Qw[i,:], t)  (second Qw stream — at roofline, FROZEN)
// Blocks 0..2559: GEMV. Block 2560: CSR sort. Block 2561: bias.
// ---------------------------------------------------------------------------
__global__ __launch_bounds__(256) void k2_wp(
    const float* __restrict__ Qw,
    const int* __restrict__ bsrc, const int* __restrict__ brow,
    const int* __restrict__ bcol, const float* __restrict__ bp_params,
    const float* __restrict__ Qb, const float* __restrict__ b) {
    const int tid = threadIdx.x;

    if (blockIdx.x >= 2560) {
        if (blockIdx.x == 2560) {
            __shared__ int c[NOUT];
            __shared__ int scan[NOUT];
            __shared__ int off[NOUT];
            for (int i = tid; i < NOUT; i += 256) c[i] = 0;
            __syncthreads();
            for (int k = tid; k < NNZ; k += 256) atomicAdd(&c[brow[k]], 1);
            __syncthreads();
            if (tid < 32) {
                int base = 0;
#pragma unroll
                for (int ch = 0; ch < NOUT / 32; ch++) {
                    int v = c[ch * 32 + tid];
#pragma unroll
                    for (int d = 1; d < 32; d <<= 1) {
                        int n = __shfl_up_sync(0xffffffffu, v, d);
                        if (tid >= d) v += n;
                    }
                    scan[ch * 32 + tid] = v + base;
                    base += __shfl_sync(0xffffffffu, v, 31);
                }
            }
            __syncthreads();
            for (int i = tid; i < NOUT; i += 256) {
                const int s = scan[i] - c[i];
                g_row_start[i] = s;
                off[i] = s;
            }
            if (tid == 0) g_row_start[NOUT] = NNZ;
            __syncthreads();
            for (int k = tid; k < NNZ; k += 256) {
                const int r = brow[k];
                const int pos = atomicAdd(&off[r], 1);
                g_pair[pos] = make_uint2(
                    (unsigned)bsrc[k] | ((unsigned)bcol[k] << 10),
                    __float_as_uint(bp_params[k]));
            }
        } else {
            __shared__ float s_part[4][RB];
            __shared__ float s_s[RB];
            const int r = tid & 63;
            const int chunk = tid >> 6;
            float acc = 0.0f;
            for (int i = chunk * 160; i < chunk * 160 + 160; i++)
                acc += Qb[i * RB + r] * b[i];
            s_part[chunk][r] = acc;
            __syncthreads();
            if (tid < RB) {
                s_s[tid] = s_part[0][tid] + s_part[1][tid] +
                           s_part[2][tid] + s_part[3][tid];
            }
            __syncthreads();
            for (int j = tid; j < NOUT; j += 256) {
                const float4* q4 = reinterpret_cast<const float4*>(Qb + j * RB);
                const float4* s4 = reinterpret_cast<const float4*>(s_s);
                float a = 0.0f;
#pragma unroll
                for (int u = 0; u < 16; u++) {
                    float4 q = q4[u];
                    float4 s = s4[u];
                    a += q.x * s.x + q.y * s.y + q.z * s.z + q.w * s.w;
                }
                g_bp[j] = a;
            }
        }
        return;
    }

    __shared__ float s_t[RW];
    for (int i = tid; i < RW; i += 256) s_t[i] = g_t[i];
    __syncthreads();

    const int warp = tid >> 5;
    const int lane = tid & 31;
    const int row0 = (blockIdx.x * 8 + warp) * 16;
    const float4* t4 = reinterpret_cast<const float4*>(s_t);

    for (int rr = 0; rr < 16; rr++) {
        const int row = row0 + rr;
        const float4* p4 = reinterpret_cast<const float4*>(Qw + (size_t)row * RW);
        float acc = 0.0f;
#pragma unroll
        for (int u = 0; u < 4; u++) {
            float4 q = p4[lane + 32 * u];
            float4 tt = t4[lane + 32 * u];
            acc += q.x * tt.x + q.y * tt.y + q.z * tt.z + q.w * tt.w;
        }
#pragma unroll
        for (int off = 16; off > 0; off >>= 1)
            acc += __shfl_xor_sync(0xffffffffu, acc, off);
        if (lane == 0) g_Wp[row] = acc;
    }
}

// ---------------------------------------------------------------------------
// K3: lin = x @ Wp^T + bp, SPLIT-K x2  (4096x512 @ 512x640)
// BM=64, BN=128, BK=16, 128 threads, 8x8 per-thread f32x2 tile (1 B/FMA).
// __launch_bounds__(128, 4): cap regs at 128 -> 4 resident blocks/SM.
// ---------------------------------------------------------------------------
__global__ __launch_bounds__(128, 4) void k3_gemm(const float* __restrict__ x) {
    __shared__ float As[16][68];
    __shared__ float Bs[16][132];

    const int tid = threadIdx.x;
    const int tx = tid & 15;
    const int ty = tid >> 4;
    const int bn0 = blockIdx.x * 128;
    const int bm0 = blockIdx.y * 64;
    const int kb  = blockIdx.z * 256;     // K half base

    const int am0 = (2 * tid + 0) >> 2, af0 = (2 * tid + 0) & 3;
    const int am1 = (2 * tid + 1) >> 2, af1 = (2 * tid + 1) & 3;
    const float* apg0 = x + (size_t)(bm0 + am0) * NIN + kb + af0 * 4;
    const float* apg1 = x + (size_t)(bm0 + am1) * NIN + kb + af1 * 4;
    int bn_[4], bf_[4];
    const float* bpg[4];
#pragma unroll
    for (int i = 0; i < 4; i++) {
        const int idx = tid + 128 * i;
        bn_[i] = idx >> 2;
        bf_[i] = idx & 3;
        bpg[i] = g_Wp + (size_t)(bn0 + bn_[i]) * NIN + kb + bf_[i] * 4;
    }

    unsigned long long acc[8][4];
#pragma unroll
    for (int i = 0; i < 8; i++)
#pragma unroll
        for (int j = 0; j < 4; j++) acc[i][j] = 0ull;

    float4 ar0 = *reinterpret_cast<const float4*>(apg0);
    float4 ar1 = *reinterpret_cast<const float4*>(apg1);
    float4 br[4];
#pragma unroll
    for (int i = 0; i < 4; i++) br[i] = *reinterpret_cast<const float4*>(bpg[i]);

    for (int kt = 0; kt < 16; kt++) {
        As[af0 * 4 + 0][am0] = ar0.x; As[af0 * 4 + 1][am0] = ar0.y;
        As[af0 * 4 + 2][am0] = ar0.z; As[af0 * 4 + 3][am0] = ar0.w;
        As[af1 * 4 + 0][am1] = ar1.x; As[af1 * 4 + 1][am1] = ar1.y;
        As[af1 * 4 + 2][am1] = ar1.z; As[af1 * 4 + 3][am1] = ar1.w;
#pragma unroll
        for (int i = 0; i < 4; i++) {
            Bs[bf_[i] * 4 + 0][bn_[i]] = br[i].x;
            Bs[bf_[i] * 4 + 1][bn_[i]] = br[i].y;
            Bs[bf_[i] * 4 + 2][bn_[i]] = br[i].z;
            Bs[bf_[i] * 4 + 3][bn_[i]] = br[i].w;
        }
        __syncthreads();
        if (kt < 15) {
            ar0 = *reinterpret_cast<const float4*>(apg0 + (kt + 1) * 16);
            ar1 = *reinterpret_cast<const float4*>(apg1 + (kt + 1) * 16);
#pragma unroll
            for (int i = 0; i < 4; i++)
                br[i] = *reinterpret_cast<const float4*>(bpg[i] + (kt + 1) * 16);
        }
#pragma unroll
        for (int kk = 0; kk < 16; kk++) {
            const float4 a0 = *reinterpret_cast<const float4*>(&As[kk][ty * 8]);
            const float4 a1 = *reinterpret_cast<const float4*>(&As[kk][ty * 8 + 4]);
            const ulonglong2 bL =
                *reinterpret_cast<const ulonglong2*>(&Bs[kk][tx * 4]);
            const ulonglong2 bH =
                *reinterpret_cast<const ulonglong2*>(&Bs[kk][64 + tx * 4]);
            unsigned long long a2[8];
            asm("mov.b64 %0, {%1, %1};" : "=l"(a2[0]) : "f"(a0.x));
            asm("mov.b64 %0, {%1, %1};" : "=l"(a2[1]) : "f"(a0.y));
            asm("mov.b64 %0, {%1, %1};" : "=l"(a2[2]) : "f"(a0.z));
            asm("mov.b64 %0, {%1, %1};" : "=l"(a2[3]) : "f"(a0.w));
            asm("mov.b64 %0, {%1, %1};" : "=l"(a2[4]) : "f"(a1.x));
            asm("mov.b64 %0, {%1, %1};" : "=l"(a2[5]) : "f"(a1.y));
            asm("mov.b64 %0, {%1, %1};" : "=l"(a2[6]) : "f"(a1.z));
            asm("mov.b64 %0, {%1, %1};" : "=l"(a2[7]) : "f"(a1.w));
#pragma unroll
            for (int i = 0; i < 8; i++) {
                asm("fma.rn.f32x2 %0, %1, %2, %0;" : "+l"(acc[i][0]) : "l"(a2[i]), "l"(bL.x));
                asm("fma.rn.f32x2 %0, %1, %2, %0;" : "+l"(acc[i][1]) : "l"(a2[i]), "l"(bL.y));
                asm("fma.rn.f32x2 %0, %1, %2, %0;" : "+l"(acc[i][2]) : "l"(a2[i]), "l"(bH.x));
                asm("fma.rn.f32x2 %0, %1, %2, %0;" : "+l"(acc[i][3]) : "l"(a2[i]), "l"(bH.y));
            }
        }
        __syncthreads();
    }

    // epilogue: z=0 adds bias -> g_lin; z=1 raw partial -> g_lin2
    float* gout = (blockIdx.z == 0) ? g_lin : g_lin2;
    float4 bv0 = make_float4(0.f, 0.f, 0.f, 0.f);
    float4 bv1 = make_float4(0.f, 0.f, 0.f, 0.f);
    if (blockIdx.z == 0) {
        bv0 = *reinterpret_cast<const float4*>(&g_bp[bn0 + tx * 4]);
        bv1 = *reinterpret_cast<const float4*>(&g_bp[bn0 + 64 + tx * 4]);
    }
#pragma unroll
    for (int i = 0; i < 8; i++) {
        const int row = bm0 + ty * 8 + i;
        float r0, r1, r2, r3, r4, r5, r6, r7;
        asm("mov.b64 {%0, %1}, %2;" : "=f"(r0), "=f"(r1) : "l"(acc[i][0]));
        asm("mov.b64 {%0, %1}, %2;" : "=f"(r2), "=f"(r3) : "l"(acc[i][1]));
        asm("mov.b64 {%0, %1}, %2;" : "=f"(r4), "=f"(r5) : "l"(acc[i][2]));
        asm("mov.b64 {%0, %1}, %2;" : "=f"(r6), "=f"(r7) : "l"(acc[i][3]));
        float* dst = gout + (size_t)row * NOUT + bn0;
        *reinterpret_cast<float4*>(dst + tx * 4) =
            make_float4(r0 + bv0.x, r1 + bv0.y, r2 + bv0.z, r3 + bv0.w);
        *reinterpret_cast<float4*>(dst + 64 + tx * 4) =
            make_float4(r4 + bv1.x, r5 + bv1.y, r6 + bv1.z, r7 + bv1.w);
    }
}

// ---------------------------------------------------------------------------
// K4a: bilinear CSR -> preact; sums the two K-half partials on load.
// LAUNCH #4 this round -> gets the ncu profile.
// Block 0 re-zeros g_t for the next graph replay.
// ---------------------------------------------------------------------------
#define K4_P 33
extern __shared__ float2 k4_s2[];   // [640][33]

__global__ __launch_bounds__(512) void k4a_bilinear(void) {
    const int tid  = threadIdx.x;
    const int warp = tid >> 5;
    const int lane = tid & 31;
    const int grp  = blockIdx.x >> 1;
    const int half = blockIdx.x & 1;
    const int b0   = grp * 64;

    if (blockIdx.x == 0) g_t[tid] = 0.0f;   // 512 threads cover RW=512

#pragma unroll
    for (int i = 0; i < 4; i++) {
        const int bb = warp + 16 * i;
        const float* src1 = g_lin  + (size_t)(b0 + bb) * NOUT;
        const float* src2 = g_lin2 + (size_t)(b0 + bb) * NOUT;
        float* base = reinterpret_cast<float*>(k4_s2) + (bb & 1);
        const int pr = bb >> 1;
        for (int ch = lane; ch < NOUT; ch += 32)
            base[(ch * K4_P + pr) * 2] = src1[ch] + src2[ch];
    }
    __syncthreads();

    const unsigned long long* s_u64 =
        reinterpret_cast<const unsigned long long*>(k4_s2) + lane;
    unsigned long long c01;
    asm("mov.b64 %0, {%1, %1};" : "=l"(c01) : "f"(0.1f));

#pragma unroll 2
    for (int i = 0; i < 20; i++) {
        const int row = half * 320 + warp + 16 * i;
        const int ks = g_row_start[row];
        const int ke = g_row_start[row + 1];
        unsigned long long a0 = 0ull, a1 = 0ull, a2c = 0ull, a3 = 0ull;
        int k = ks;
#define K4_STEP(ACC, PR)                                                      \
        {                                                                     \
            unsigned long long av = s_u64[((PR).x & 1023) * K4_P];            \
            unsigned long long bv = s_u64[(((PR).x >> 10) & 1023) * K4_P];    \
            const float pf = __uint_as_float((PR).y);                         \
            unsigned long long pp, t;                                         \
            asm("mov.b64 %0, {%1, %1};" : "=l"(pp) : "f"(pf));                \
            asm("mul.rn.f32x2 %0, %1, %2;" : "=l"(t) : "l"(av), "l"(bv));     \
            asm("fma.rn.f32x2 %0, %1, %2, %0;" : "+l"(ACC) : "l"(t), "l"(pp));\
        }
        for (; k + 3 < ke; k += 4) {
            const uint2 p0 = g_pair[k + 0];
            const uint2 p1 = g_pair[k + 1];
            const uint2 p2 = g_pair[k + 2];
            const uint2 p3 = g_pair[k + 3];
            K4_STEP(a0, p0)
            K4_STEP(a1, p1)
            K4_STEP(a2c, p2)
            K4_STEP(a3, p3)
        }
        for (; k < ke; k++) {
            const uint2 p0 = g_pair[k];
            K4_STEP(a0, p0)
        }
        unsigned long long acc;
        asm("add.rn.f32x2 %0, %1, %2;" : "=l"(acc) : "l"(a0), "l"(a1));
        asm("add.rn.f32x2 %0, %1, %2;" : "+l"(acc) : "l"(acc), "l"(a2c));
        asm("add.rn.f32x2 %0, %1, %2;" : "+l"(acc) : "l"(acc), "l"(a3));

        unsigned long long linv = s_u64[row * K4_P];
        unsigned long long pv;
        asm("mul.rn.f32x2 %0, %1, %2;" : "=l"(pv) : "l"(acc), "l"(c01));
        asm("add.rn.f32x2 %0, %1, %2;" : "+l"(pv) : "l"(pv), "l"(linv));
        *reinterpret_cast<unsigned long long*>(
            g_pre + (size_t)row * BATCH + b0 + 2 * lane) = pv;
    }
}

// ---------------------------------------------------------------------------
// K4b: gated nonlinearity from transposed preact (FROZEN, ~6us)
// ---------------------------------------------------------------------------
__global__ __launch_bounds__(256) void k4b_gate(
    const int* __restrict__ gate_idx, float* __restrict__ out) {
    __shared__ float s_t[32][257];
    const int tid = threadIdx.x;
    const int b0 = blockIdx.x * 256;
    const int j0 = blockIdx.y * 32;

#pragma unroll 4
    for (int jj = 0; jj < 32; jj++) {
        const int j = j0 + jj;
        const int gi = gate_idx[j];
        const float v = g_pre[(size_t)j * BATCH + b0 + tid];
        const float g = g_pre[(size_t)gi * BATCH + b0 + tid];
        s_t[jj][tid] = v / (1.0f + __expf(-g));
    }
    __syncthreads();

    float* dst = out + (size_t)(b0 + tid) * NREP + j0;
#pragma unroll
    for (int q = 0; q < 8; q++) {
        float4 v = make_float4(s_t[q * 4 + 0][tid], s_t[q * 4 + 1][tid],
                               s_t[q * 4 + 2][tid], s_t[q * 4 + 3][tid]);
        *reinterpret_cast<float4*>(dst + q * 4) = v;
    }
}

// ---------------------------------------------------------------------------
// Launch
// ---------------------------------------------------------------------------
extern "C" void kernel_launch(void* const* d_in, const int* in_sizes, int n_in,
                              void* d_out, int out_size) {
    const float* x        = (const float*)d_in[0];
    const float* W_weight = (const float*)d_in[1];
    const float* b        = (const float*)d_in[2];
    const float* Qw       = (const float*)d_in[3];
    const float* Qb       = (const float*)d_in[4];
    const float* bi_p     = (const float*)d_in[5];
    const int*   bi_src   = (const int*)d_in[6];
    const int*   bi_row   = (const int*)d_in[7];
    const int*   bi_col   = (const int*)d_in[8];
    const int*   gate_idx = (const int*)d_in[9];
    float* out = (float*)d_out;

    static int smem_set = 0;
    const int k4_smem_bytes = NOUT * K4_P * sizeof(float2);  // 168,960
    if (!smem_set) {
        cudaFuncSetAttribute(k4a_bilinear,
                             cudaFuncAttributeMaxDynamicSharedMemorySize,
                             k4_smem_bytes);
        smem_set = 1;
    }

    k1_qwt<<<1280, 512>>>(Qw, W_weight);
    k2_wp<<<2562, 256>>>(Qw, bi_src, bi_row, bi_col, bi_p, Qb, b);
    k3_gemm<<<dim3(NOUT / 128, BATCH / 64, 2), 128>>>(x);
    k4a_bilinear<<<128, 512, k4_smem_bytes>>>();   // launch #4 -> profiled
    k4b_gate<<<dim3(BATCH / 256, NREP / 32), 256>>>(gate_idx, out);
}